// round 2
// baseline (speedup 1.0000x reference)
#include <cuda_runtime.h>
#include <math.h>

#define B_   16
#define CIN  256
#define COUT 512
#define HIN  128
#define WIN  128
#define HB   129   // blurred intermediate H
#define WBL  129   // blurred intermediate W
#define OH   64
#define OW   64

// Scratch for the blurred intermediate: [16,256,129,129] fp32 = 272.6 MB.
static __device__ float g_blur[(size_t)B_ * CIN * HB * WBL];

// ---------------------------------------------------------------------------
// Stage 1: 4x4 blur (kernel = outer([1,3,3,1])/64, symmetric => flip is a noop)
// y[h,w] = sum_{i,j} k[i]k[j] * x[h+i-2, w+j-2], h,w in [0,129), zero-padded.
// Memory-bound: ~270MB read + 273MB write.
// ---------------------------------------------------------------------------
__global__ void blur_kernel(const float* __restrict__ x) {
    __shared__ float tile[11][36];
    const int ch = blockIdx.z;              // b*CIN + c
    const int w0 = blockIdx.x * 32;
    const int h0 = blockIdx.y * 8;
    const float* xin = x + (size_t)ch * (HIN * WIN);

    const int tid = threadIdx.y * 32 + threadIdx.x;
    // Load 11 x 35 input patch (rows h0-2..h0+8, cols w0-2..w0+32), zero pad.
    for (int idx = tid; idx < 11 * 35; idx += 256) {
        int rr = idx / 35, cc2 = idx - rr * 35;
        int r = h0 - 2 + rr, c = w0 - 2 + cc2;
        float v = 0.f;
        if ((unsigned)r < HIN && (unsigned)c < WIN) v = xin[r * WIN + c];
        tile[rr][cc2] = v;
    }
    __syncthreads();

    const int ow = w0 + threadIdx.x, oh = h0 + threadIdx.y;
    if (ow < WBL && oh < HB) {
        const float kb[4] = {0.125f, 0.375f, 0.375f, 0.125f};
        float s = 0.f;
#pragma unroll
        for (int i = 0; i < 4; i++)
#pragma unroll
            for (int j = 0; j < 4; j++)
                s += (kb[i] * kb[j]) * tile[threadIdx.y + i][threadIdx.x + j];
        g_blur[(size_t)ch * (HB * WBL) + oh * WBL + ow] = s;
    }
}

// ---------------------------------------------------------------------------
// Stage 2: 3x3 stride-2 conv (EqualConv2d, scale=1/48) + bias + leaky(0.2)*sqrt2
// Block: 64 oc x (4 rows x 32 cols) output tile. 256 threads.
// Thread: 8 oc (stride 8) x 4 rows, fixed col = lane. 32 accumulators.
// SMEM input is parity-split so stride-2 column reads become stride-1
// (conflict-free); weight reads are warp-uniform (broadcast).
// FMA:LDS = 96:36 per (c, kh) step -> FFMA-issue bound.
// ---------------------------------------------------------------------------
__global__ void __launch_bounds__(256) conv_kernel(
    const float* __restrict__ wsrc,   // [3][3][CIN][COUT]
    const float* __restrict__ bias,   // [COUT]
    float* __restrict__ out)          // [B][COUT][64][64]
{
    __shared__ float in_s[8][9][2][34];   // 8 ch x 9 rows x parity x 33(+pad)
    __shared__ float w_s[8][9][64];       // 8 ch x 9 taps x 64 oc

    const int tile_r = blockIdx.x >> 1;
    const int tile_c = blockIdx.x & 1;
    const int hb  = tile_r * 4;           // output row base (0..60)
    const int wb  = tile_c * 32;          // output col base (0 or 32)
    const int oc0 = blockIdx.y * 64;
    const int b   = blockIdx.z;

    const int tid  = threadIdx.x;
    const int lane = tid & 31;
    const int toc  = tid >> 5;            // warp id = oc subgroup

    const float* gb = g_blur + (size_t)b * (CIN * HB * WBL);

    float acc[8][4];
#pragma unroll
    for (int i = 0; i < 8; i++)
#pragma unroll
        for (int r = 0; r < 4; r++) acc[i][r] = 0.f;

    const float scale = 1.0f / 48.0f;     // 1/sqrt(256*9)

    for (int cc = 0; cc < CIN / 8; cc++) {
        const int c0 = cc * 8;

        // Input patch: 8 ch x 9 rows x 65 cols. Rows 2*hb..2*hb+8 (max 128),
        // cols 2*wb..2*wb+64 (max 128) -- always in range, no bounds checks.
        for (int idx = tid; idx < 8 * 9 * 65; idx += 256) {
            int c   = idx / 585;
            int rem = idx - c * 585;
            int ir  = rem / 65;
            int jc  = rem - ir * 65;
            float v = gb[(size_t)(c0 + c) * (HB * WBL)
                         + (2 * hb + ir) * WBL + (2 * wb + jc)];
            in_s[c][ir][jc & 1][jc >> 1] = v;
        }
        // Weights: [tap][cin][cout] slice, equalized-lr scale folded in.
        for (int idx = tid; idx < 8 * 9 * 64; idx += 256) {
            int c   = idx / 576;
            int rem = idx - c * 576;
            int tap = rem / 64;
            int o   = rem - tap * 64;
            w_s[c][tap][o] =
                wsrc[(size_t)(tap * CIN + c0 + c) * COUT + oc0 + o] * scale;
        }
        __syncthreads();

#pragma unroll 4
        for (int c = 0; c < 8; c++) {
#pragma unroll
            for (int a = 0; a < 3; a++) {
                // Input col for output col (wb+lane), tap bb: 2*lane + bb.
                // bb=0 -> parity0 j=lane; bb=1 -> parity1 j=lane; bb=2 -> parity0 j=lane+1.
                float x0[4], x1[4], x2[4];
#pragma unroll
                for (int r = 0; r < 4; r++) {
                    x0[r] = in_s[c][2 * r + a][0][lane];
                    x1[r] = in_s[c][2 * r + a][1][lane];
                    x2[r] = in_s[c][2 * r + a][0][lane + 1];
                }
#pragma unroll
                for (int i = 0; i < 8; i++) {
                    float w0 = w_s[c][a * 3 + 0][toc + 8 * i];
                    float w1 = w_s[c][a * 3 + 1][toc + 8 * i];
                    float w2 = w_s[c][a * 3 + 2][toc + 8 * i];
#pragma unroll
                    for (int r = 0; r < 4; r++) {
                        acc[i][r] = fmaf(w0, x0[r], acc[i][r]);
                        acc[i][r] = fmaf(w1, x1[r], acc[i][r]);
                        acc[i][r] = fmaf(w2, x2[r], acc[i][r]);
                    }
                }
            }
        }
        __syncthreads();
    }

    // Epilogue: bias + leaky_relu(0.2) * sqrt(2). Coalesced 32-float stores.
    const float g = 1.41421356237309515f;
#pragma unroll
    for (int i = 0; i < 8; i++) {
        int oc = oc0 + toc + 8 * i;
        float bv = __ldg(&bias[oc]);
#pragma unroll
        for (int r = 0; r < 4; r++) {
            float v = acc[i][r] + bv;
            v = (v > 0.f ? v : 0.2f * v) * g;
            out[(size_t)((b * COUT + oc) * OH + hb + r) * OW + wb + lane] = v;
        }
    }
}

extern "C" void kernel_launch(void* const* d_in, const int* in_sizes, int n_in,
                              void* d_out, int out_size) {
    const float* x    = (const float*)d_in[0];   // [16,256,128,128]
    const float* w    = (const float*)d_in[1];   // [3,3,256,512]
    const float* bias = (const float*)d_in[2];   // [512]
    float* out = (float*)d_out;                  // [16,512,64,64]

    dim3 bblk(32, 8);
    dim3 bgrd((WBL + 31) / 32, (HB + 7) / 8, B_ * CIN);   // (5, 17, 4096)
    blur_kernel<<<bgrd, bblk>>>(x);

    dim3 cgrd(32, 8, B_);                                 // spatial, oc-tile, batch
    conv_kernel<<<cgrd, 256>>>(w, bias, out);
}

// round 4
// speedup vs baseline: 3.2318x; 3.2318x over previous
#include <cuda_runtime.h>
#include <cuda_bf16.h>
#include <cstdint>

#define B_    16
#define CIN   256
#define COUT  512
#define HB2   129   // blurred H/W

// Scratch: blurred intermediate in NHWC bf16 (hi/lo split), weights transposed.
static __device__ __align__(128) __nv_bfloat16 g_xh[(size_t)B_ * HB2 * HB2 * CIN];
static __device__ __align__(128) __nv_bfloat16 g_xl[(size_t)B_ * HB2 * HB2 * CIN];
static __device__ __align__(128) __nv_bfloat16 g_wh[9 * COUT * CIN];
static __device__ __align__(128) __nv_bfloat16 g_wl[9 * COUT * CIN];

// ---------------------------------------------------------------------------
__device__ __forceinline__ uint32_t smem_u32(const void* p) {
    uint32_t a;
    asm("{ .reg .u64 t; cvta.to.shared.u64 t, %1; cvt.u32.u64 %0, t; }" : "=r"(a) : "l"(p));
    return a;
}
__device__ __forceinline__ void cp16(uint32_t d, const void* s) {
    asm volatile("cp.async.cg.shared.global [%0], [%1], 16;" :: "r"(d), "l"(s));
}
__device__ __forceinline__ void cp_commit() {
    asm volatile("cp.async.commit_group;" ::: "memory");
}
__device__ __forceinline__ void cp_wait1() {
    asm volatile("cp.async.wait_group 1;" ::: "memory");
}
__device__ __forceinline__ void ldsm4(uint32_t* r, uint32_t a) {
    asm volatile("ldmatrix.sync.aligned.m8n8.x4.shared.b16 {%0,%1,%2,%3}, [%4];"
                 : "=r"(r[0]), "=r"(r[1]), "=r"(r[2]), "=r"(r[3]) : "r"(a));
}
__device__ __forceinline__ void mma16816(float* c, const uint32_t* a, const uint32_t* b) {
    asm volatile(
        "mma.sync.aligned.m16n8k16.row.col.f32.bf16.bf16.f32 "
        "{%0,%1,%2,%3}, {%4,%5,%6,%7}, {%8,%9}, {%0,%1,%2,%3};"
        : "+f"(c[0]), "+f"(c[1]), "+f"(c[2]), "+f"(c[3])
        : "r"(a[0]), "r"(a[1]), "r"(a[2]), "r"(a[3]), "r"(b[0]), "r"(b[1]));
}

// ---------------------------------------------------------------------------
// Stage 1: 4x4 blur, NCHW fp32 -> NHWC bf16 hi/lo.  Tile: 16ch x 8h x 32w.
// ---------------------------------------------------------------------------
__global__ void __launch_bounds__(256) blur_kernel(const float* __restrict__ x) {
    __shared__ float tile[16][11][36];
    const int w0 = blockIdx.x * 32, h0 = blockIdx.y * 8;
    const int b = blockIdx.z >> 4, c0 = (blockIdx.z & 15) * 16;
    const int tid = threadIdx.y * 32 + threadIdx.x;

    for (int idx = tid; idx < 16 * 11 * 35; idx += 256) {
        int c = idx / 385, rem = idx - c * 385;
        int rr = rem / 35, cc = rem - rr * 35;
        int r = h0 - 2 + rr, col = w0 - 2 + cc;
        float v = 0.f;
        if ((unsigned)r < 128u && (unsigned)col < 128u)
            v = x[(((size_t)b * CIN + c0 + c) * 128 + r) * 128 + col];
        tile[c][rr][cc] = v;
    }
    __syncthreads();

    const int ow = w0 + threadIdx.x, oh = h0 + threadIdx.y;
    if (ow < HB2 && oh < HB2) {
        const float kb[4] = {0.125f, 0.375f, 0.375f, 0.125f};
        float s[16];
#pragma unroll
        for (int c = 0; c < 16; c++) {
            float acc = 0.f;
#pragma unroll
            for (int i = 0; i < 4; i++)
#pragma unroll
                for (int j = 0; j < 4; j++)
                    acc += (kb[i] * kb[j]) * tile[c][threadIdx.y + i][threadIdx.x + j];
            s[c] = acc;
        }
        unsigned hp[8], lp[8];
#pragma unroll
        for (int c = 0; c < 8; c++) {
            __nv_bfloat16 h0b = __float2bfloat16(s[2 * c]);
            __nv_bfloat16 h1b = __float2bfloat16(s[2 * c + 1]);
            __nv_bfloat16 l0b = __float2bfloat16(s[2 * c] - __bfloat162float(h0b));
            __nv_bfloat16 l1b = __float2bfloat16(s[2 * c + 1] - __bfloat162float(h1b));
            hp[c] = (unsigned)__bfloat16_as_ushort(h0b) | ((unsigned)__bfloat16_as_ushort(h1b) << 16);
            lp[c] = (unsigned)__bfloat16_as_ushort(l0b) | ((unsigned)__bfloat16_as_ushort(l1b) << 16);
        }
        size_t base = (((size_t)b * HB2 + oh) * HB2 + ow) * CIN + c0;
        ((uint4*)(g_xh + base))[0] = make_uint4(hp[0], hp[1], hp[2], hp[3]);
        ((uint4*)(g_xh + base))[1] = make_uint4(hp[4], hp[5], hp[6], hp[7]);
        ((uint4*)(g_xl + base))[0] = make_uint4(lp[0], lp[1], lp[2], lp[3]);
        ((uint4*)(g_xl + base))[1] = make_uint4(lp[4], lp[5], lp[6], lp[7]);
    }
}

// ---------------------------------------------------------------------------
// Weight prep: w[3][3][CIN][COUT] fp32 -> g_wh/g_wl[tap][COUT][CIN] bf16, *1/48
// ---------------------------------------------------------------------------
__global__ void __launch_bounds__(256) wprep_kernel(const float* __restrict__ w) {
    __shared__ float t[32][33];
    const int tap = blockIdx.z, o0 = blockIdx.x * 32, cb0 = blockIdx.y * 32;
    const int tx = threadIdx.x, ty = threadIdx.y;
    const float sc = 1.0f / 48.0f;
    for (int r = ty; r < 32; r += 8)
        t[r][tx] = w[((size_t)tap * CIN + cb0 + r) * COUT + o0 + tx] * sc;
    __syncthreads();
    for (int r = ty; r < 32; r += 8) {
        float v = t[tx][r];
        __nv_bfloat16 h = __float2bfloat16(v);
        __nv_bfloat16 l = __float2bfloat16(v - __bfloat162float(h));
        size_t off = ((size_t)tap * COUT + o0 + r) * CIN + cb0 + tx;
        g_wh[off] = h;
        g_wl[off] = l;
    }
}

// ---------------------------------------------------------------------------
// Stage 2: implicit GEMM via mma.sync (HMMA bf16, fp32 accum), 3-pass hi/lo.
// CTA: 256 thr, tile M=128 px x N=128 oc, K=2304 in 72 chunks of 32.
// 8 warps = 4(m) x 2(n); warp tile 32x64. cp.async double buffer.
// SMEM tile stride 40 bf16 -> conflict-free ldmatrix.
// ---------------------------------------------------------------------------
#define TSTR  40                    // bf16 elements per smem row
#define ABUF  10240                 // bytes per 128x40 bf16 tile
#define BUFB  (4 * ABUF)            // Ah, Al, Bh, Bl
#define SMEM_BYTES (2 * BUFB)       // 81920

__global__ void __launch_bounds__(256) conv_mma_kernel(
    const float* __restrict__ bias, float* __restrict__ out)
{
    extern __shared__ char smem[];
    const uint32_t sA = smem_u32(smem);
    const int tid = threadIdx.x, lane = tid & 31, wid = tid >> 5;
    const int hb  = blockIdx.x * 2;     // 2 output rows per CTA
    const int oc0 = blockIdx.y * 128;
    const int b   = blockIdx.z;
    const int wm  = (wid & 3) * 32;     // warp m offset
    const int wn  = (wid >> 2) * 64;    // warp n offset

    float acc[2][8][4];
#pragma unroll
    for (int i = 0; i < 2; i++)
#pragma unroll
        for (int j = 0; j < 8; j++)
#pragma unroll
            for (int k = 0; k < 4; k++) acc[i][j][k] = 0.f;

    // Load mapping: thread -> row r (0..127), 2 x 16B segments.
    const int r  = tid >> 1;
    const int sg = (tid & 1) * 2;       // segment pair base (each seg = 8 bf16)
    const int oh = hb + (r >> 6), ow = r & 63;

#define ISSUE_LOADS(chunk, buf)                                                  \
    {                                                                            \
        const int tap = (chunk) >> 3, c0 = ((chunk) & 7) << 5;                   \
        const int kh = tap / 3, kw = tap - kh * 3;                               \
        const size_t ao = (((size_t)(b * HB2 + 2 * oh + kh)) * HB2               \
                           + (2 * ow + kw)) * CIN + c0 + sg * 8;                 \
        const size_t bo = ((size_t)(tap * COUT + oc0 + r)) * CIN + c0 + sg * 8;  \
        const uint32_t d = sA + (buf) * BUFB + (r * TSTR + sg * 8) * 2;          \
        cp16(d,            g_xh + ao); cp16(d + 16,            g_xh + ao + 8);   \
        cp16(d + ABUF,     g_xl + ao); cp16(d + ABUF + 16,     g_xl + ao + 8);   \
        cp16(d + 2*ABUF,   g_wh + bo); cp16(d + 2*ABUF + 16,   g_wh + bo + 8);   \
        cp16(d + 3*ABUF,   g_wl + bo); cp16(d + 3*ABUF + 16,   g_wl + bo + 8);   \
    }

    ISSUE_LOADS(0, 0); cp_commit();
    ISSUE_LOADS(1, 1); cp_commit();

    for (int i = 0; i < 72; i++) {
        cp_wait1();
        __syncthreads();
        const uint32_t base = sA + (i & 1) * BUFB;

#pragma unroll
        for (int ks = 0; ks < 32; ks += 16) {
            uint32_t ah[2][4], al[2][4], bh[4][4], bl[4][4];
#pragma unroll
            for (int mt = 0; mt < 2; mt++) {
                uint32_t a = base + ((wm + mt * 16 + (lane & 15)) * TSTR
                                     + ks + ((lane & 16) >> 1)) * 2;
                ldsm4(ah[mt], a);
                ldsm4(al[mt], a + ABUF);
            }
#pragma unroll
            for (int bt = 0; bt < 4; bt++) {
                uint32_t a = base + 2 * ABUF
                           + ((wn + bt * 16 + (lane & 7) + ((lane & 16) >> 1)) * TSTR
                              + ks + (lane & 8)) * 2;
                ldsm4(bh[bt], a);
                ldsm4(bl[bt], a + ABUF);
            }
#pragma unroll
            for (int mt = 0; mt < 2; mt++)
#pragma unroll
                for (int bt = 0; bt < 4; bt++)
#pragma unroll
                    for (int h = 0; h < 2; h++) {
                        const int nt = bt * 2 + h;
                        mma16816(acc[mt][nt], ah[mt], &bh[bt][2 * h]);
                        mma16816(acc[mt][nt], ah[mt], &bl[bt][2 * h]);
                        mma16816(acc[mt][nt], al[mt], &bh[bt][2 * h]);
                    }
        }
        __syncthreads();
        if (i + 2 < 72) ISSUE_LOADS(i + 2, i & 1);
        cp_commit();
    }

    // Epilogue: stage [oc_local][px] fp32 in smem, then coalesced writes.
    float* so = (float*)smem;           // 128 x 132 floats = 67.6KB <= 80KB
#pragma unroll
    for (int mt = 0; mt < 2; mt++)
#pragma unroll
        for (int nt = 0; nt < 8; nt++)
#pragma unroll
            for (int k = 0; k < 4; k++) {
                int px  = wm + mt * 16 + (lane >> 2) + ((k & 2) ? 8 : 0);
                int ocl = wn + nt * 8 + (lane & 3) * 2 + (k & 1);
                so[ocl * 132 + px] = acc[mt][nt][k];
            }
    __syncthreads();

    const int ocl = tid >> 1, pxb = (tid & 1) * 64;
    const float bv = bias[oc0 + ocl];
    const float gsc = 1.41421356237309515f;
    float* dst = out + (((size_t)(b * COUT + oc0 + ocl) * 64) + hb + (tid & 1)) * 64;
#pragma unroll
    for (int j = 0; j < 64; j += 4) {
        float4 v = *(const float4*)(so + ocl * 132 + pxb + j);
        v.x = ((v.x + bv) > 0.f ? (v.x + bv) : 0.2f * (v.x + bv)) * gsc;
        v.y = ((v.y + bv) > 0.f ? (v.y + bv) : 0.2f * (v.y + bv)) * gsc;
        v.z = ((v.z + bv) > 0.f ? (v.z + bv) : 0.2f * (v.z + bv)) * gsc;
        v.w = ((v.w + bv) > 0.f ? (v.w + bv) : 0.2f * (v.w + bv)) * gsc;
        *(float4*)(dst + j) = v;
    }
}

// ---------------------------------------------------------------------------
extern "C" void kernel_launch(void* const* d_in, const int* in_sizes, int n_in,
                              void* d_out, int out_size) {
    const float* x    = (const float*)d_in[0];   // [16,256,128,128]
    const float* w    = (const float*)d_in[1];   // [3,3,256,512]
    const float* bias = (const float*)d_in[2];   // [512]
    float* out = (float*)d_out;                  // [16,512,64,64]

    cudaFuncSetAttribute(conv_mma_kernel,
                         cudaFuncAttributeMaxDynamicSharedMemorySize, SMEM_BYTES);

    blur_kernel<<<dim3(5, 17, B_ * 16), dim3(32, 8)>>>(x);
    wprep_kernel<<<dim3(16, 8, 9), dim3(32, 8)>>>(w);
    conv_mma_kernel<<<dim3(32, 4, B_), 256, SMEM_BYTES>>>(bias, out);
}

// round 5
// speedup vs baseline: 4.8094x; 1.4882x over previous
#include <cuda_runtime.h>
#include <cuda_fp16.h>
#include <cstdint>

#define B_    16
#define CIN   256
#define COUT  512
#define HB2   129   // blurred H/W

// Scratch: blurred intermediate NHWC fp16; weights [tap][oc][cin] fp16.
static __device__ __align__(128) __half g_x[(size_t)B_ * HB2 * HB2 * CIN];
static __device__ __align__(128) __half g_w[9 * COUT * CIN];

// ---------------------------------------------------------------------------
__device__ __forceinline__ uint32_t smem_u32(const void* p) {
    uint32_t a;
    asm("{ .reg .u64 t; cvta.to.shared.u64 t, %1; cvt.u32.u64 %0, t; }" : "=r"(a) : "l"(p));
    return a;
}
__device__ __forceinline__ void cp16(uint32_t d, const void* s) {
    asm volatile("cp.async.cg.shared.global [%0], [%1], 16;" :: "r"(d), "l"(s));
}
__device__ __forceinline__ void cp_commit() {
    asm volatile("cp.async.commit_group;" ::: "memory");
}
__device__ __forceinline__ void cp_wait1() {
    asm volatile("cp.async.wait_group 1;" ::: "memory");
}
__device__ __forceinline__ void ldsm4(uint32_t* r, uint32_t a) {
    asm volatile("ldmatrix.sync.aligned.m8n8.x4.shared.b16 {%0,%1,%2,%3}, [%4];"
                 : "=r"(r[0]), "=r"(r[1]), "=r"(r[2]), "=r"(r[3]) : "r"(a));
}
__device__ __forceinline__ void mma16816(float* c, const uint32_t* a, const uint32_t* b) {
    asm volatile(
        "mma.sync.aligned.m16n8k16.row.col.f32.f16.f16.f32 "
        "{%0,%1,%2,%3}, {%4,%5,%6,%7}, {%8,%9}, {%0,%1,%2,%3};"
        : "+f"(c[0]), "+f"(c[1]), "+f"(c[2]), "+f"(c[3])
        : "r"(a[0]), "r"(a[1]), "r"(a[2]), "r"(a[3]), "r"(b[0]), "r"(b[1]));
}

// ---------------------------------------------------------------------------
// Stage 1: separable 4x4 blur, NCHW fp32 -> NHWC fp16.
// Tile: 16 ch x 8 h x 32 w outputs. No integer division anywhere.
// H-pass into smem, V-pass from smem. kb = [1,3,3,1]/8 per axis.
// ---------------------------------------------------------------------------
__global__ void __launch_bounds__(256) blur_kernel(const float* __restrict__ x) {
    __shared__ float tile[16][11][36];
    __shared__ float hbuf[16][11][33];
    const int w0 = blockIdx.x * 32, h0 = blockIdx.y * 8;
    const int b = blockIdx.z >> 4, c0 = (blockIdx.z & 15) * 16;
    const int tx = threadIdx.x, ty = threadIdx.y;

    // Load 11 x 35 per channel: rows {ty, ty+8}, cols {tx, tx+32 (tx<3)}.
    const float* xb = x + ((size_t)b * CIN + c0) * (128 * 128);
#pragma unroll 4
    for (int c = 0; c < 16; c++) {
        const float* xc = xb + (size_t)c * (128 * 128);
#pragma unroll
        for (int rv = 0; rv < 2; rv++) {
            int rr = ty + rv * 8;
            if (rr < 11) {
                int r = h0 - 2 + rr;
                int cl = w0 - 2 + tx;
                float v0 = 0.f, v1 = 0.f;
                if ((unsigned)r < 128u) {
                    if ((unsigned)cl < 128u)        v0 = xc[r * 128 + cl];
                    if (tx < 3 && (unsigned)(cl + 32) < 128u) v1 = xc[r * 128 + cl + 32];
                }
                tile[c][rr][tx] = v0;
                if (tx < 3) tile[c][rr][tx + 32] = v1;
            }
        }
    }
    __syncthreads();

    // H-pass: 11 rows x 32 cols per channel.
#pragma unroll 4
    for (int c = 0; c < 16; c++) {
#pragma unroll
        for (int rv = 0; rv < 2; rv++) {
            int rr = ty + rv * 8;
            if (rr < 11) {
                float s = 0.125f * (tile[c][rr][tx] + tile[c][rr][tx + 3])
                        + 0.375f * (tile[c][rr][tx + 1] + tile[c][rr][tx + 2]);
                hbuf[c][rr][tx] = s;
            }
        }
    }
    __syncthreads();

    // V-pass + fp16 pack + store (16 ch = 32B per thread, sector-aligned).
    const int ow = w0 + tx, oh = h0 + ty;
    if (ow < HB2 && oh < HB2) {
        unsigned pk[8];
#pragma unroll
        for (int c = 0; c < 8; c++) {
            float s0 = 0.125f * (hbuf[2*c][ty][tx] + hbuf[2*c][ty + 3][tx])
                     + 0.375f * (hbuf[2*c][ty + 1][tx] + hbuf[2*c][ty + 2][tx]);
            float s1 = 0.125f * (hbuf[2*c+1][ty][tx] + hbuf[2*c+1][ty + 3][tx])
                     + 0.375f * (hbuf[2*c+1][ty + 1][tx] + hbuf[2*c+1][ty + 2][tx]);
            __half2 h = __floats2half2_rn(s0, s1);
            pk[c] = *(unsigned*)&h;
        }
        size_t base = (((size_t)b * HB2 + oh) * HB2 + ow) * CIN + c0;
        ((uint4*)(g_x + base))[0] = make_uint4(pk[0], pk[1], pk[2], pk[3]);
        ((uint4*)(g_x + base))[1] = make_uint4(pk[4], pk[5], pk[6], pk[7]);
    }
}

// ---------------------------------------------------------------------------
// Weight prep: w[3][3][CIN][COUT] fp32 -> g_w[tap][COUT][CIN] fp16, * 1/48.
// ---------------------------------------------------------------------------
__global__ void __launch_bounds__(256) wprep_kernel(const float* __restrict__ w) {
    __shared__ float t[32][33];
    const int tap = blockIdx.z, o0 = blockIdx.x * 32, cb0 = blockIdx.y * 32;
    const int tx = threadIdx.x, ty = threadIdx.y;
    const float sc = 1.0f / 48.0f;
    for (int r = ty; r < 32; r += 8)
        t[r][tx] = w[((size_t)tap * CIN + cb0 + r) * COUT + o0 + tx] * sc;
    __syncthreads();
    for (int r = ty; r < 32; r += 8)
        g_w[((size_t)tap * COUT + o0 + r) * CIN + cb0 + tx] = __float2half_rn(t[tx][r]);
}

// ---------------------------------------------------------------------------
// Stage 2: implicit GEMM via mma.sync (HMMA fp16 in, fp32 accum), SINGLE pass.
// CTA: 256 thr, tile M=128 px x N=128 oc, K=2304 in 36 chunks of 64.
// 8 warps = 4(m) x 2(n); warp tile 32x64. cp.async double buffer.
// SMEM stride 72 fp16 (144B): ldmatrix + cp.async both at minimum phases.
// ---------------------------------------------------------------------------
#define TSTR  72                    // fp16 elements per smem row
#define TILEB 18432                 // bytes per 128 x 72 fp16 tile
#define BUFB  (2 * TILEB)           // A tile + B tile
#define SMEM_BYTES (2 * BUFB)       // 73728

__global__ void __launch_bounds__(256) conv_mma_kernel(
    const float* __restrict__ bias, float* __restrict__ out)
{
    extern __shared__ char smem[];
    const uint32_t sA = smem_u32(smem);
    const int tid = threadIdx.x, lane = tid & 31, wid = tid >> 5;
    const int hb  = blockIdx.x * 2;     // 2 output rows per CTA
    const int oc0 = blockIdx.y * 128;
    const int b   = blockIdx.z;
    const int wm  = (wid & 3) * 32;     // warp m offset
    const int wn  = (wid >> 2) * 64;    // warp n offset

    float acc[2][8][4];
#pragma unroll
    for (int i = 0; i < 2; i++)
#pragma unroll
        for (int j = 0; j < 8; j++)
#pragma unroll
            for (int k = 0; k < 4; k++) acc[i][j][k] = 0.f;

    // Load mapping: thread -> row r (0..127) + k-half (32 elems = 64B).
    const int r  = tid >> 1;
    const int hk = tid & 1;
    const int oh = hb + (r >> 6), ow = r & 63;

#define ISSUE_LOADS(chunk, buf)                                                  \
    {                                                                            \
        const int tap = (chunk) >> 2, c0 = ((chunk) & 3) << 6;                   \
        const int kh = tap / 3, kw = tap - kh * 3;                               \
        const size_t ao = (((size_t)(b * HB2 + 2 * oh + kh)) * HB2               \
                           + (2 * ow + kw)) * CIN + c0 + hk * 32;                \
        const size_t bo = ((size_t)(tap * COUT + oc0 + r)) * CIN + c0 + hk * 32; \
        const uint32_t d = sA + (buf) * BUFB + r * 144 + hk * 64;                \
        cp16(d,      g_x + ao);      cp16(d + 16, g_x + ao + 8);                 \
        cp16(d + 32, g_x + ao + 16); cp16(d + 48, g_x + ao + 24);                \
        const uint32_t e = d + TILEB;                                            \
        cp16(e,      g_w + bo);      cp16(e + 16, g_w + bo + 8);                 \
        cp16(e + 32, g_w + bo + 16); cp16(e + 48, g_w + bo + 24);                \
    }

    ISSUE_LOADS(0, 0); cp_commit();
    ISSUE_LOADS(1, 1); cp_commit();

    for (int i = 0; i < 36; i++) {
        cp_wait1();
        __syncthreads();
        const uint32_t base = sA + (i & 1) * BUFB;

#pragma unroll
        for (int ks = 0; ks < 64; ks += 16) {
            uint32_t af[2][4], bf[4][4];
#pragma unroll
            for (int mt = 0; mt < 2; mt++) {
                uint32_t a = base + ((wm + mt * 16 + (lane & 15)) * TSTR
                                     + ks + ((lane & 16) >> 1)) * 2;
                ldsm4(af[mt], a);
            }
#pragma unroll
            for (int bt = 0; bt < 4; bt++) {
                uint32_t a = base + TILEB
                           + ((wn + bt * 16 + (lane & 7) + ((lane & 16) >> 1)) * TSTR
                              + ks + (lane & 8)) * 2;
                ldsm4(bf[bt], a);
            }
#pragma unroll
            for (int mt = 0; mt < 2; mt++)
#pragma unroll
                for (int bt = 0; bt < 4; bt++)
#pragma unroll
                    for (int h = 0; h < 2; h++)
                        mma16816(acc[mt][bt * 2 + h], af[mt], &bf[bt][2 * h]);
        }
        __syncthreads();
        if (i + 2 < 36) ISSUE_LOADS(i + 2, i & 1);
        cp_commit();
    }

    // Epilogue: stage [oc_local][px] fp32 in smem, then coalesced writes.
    float* so = (float*)smem;           // 128 x 132 floats = 67.6KB <= 72KB
#pragma unroll
    for (int mt = 0; mt < 2; mt++)
#pragma unroll
        for (int nt = 0; nt < 8; nt++)
#pragma unroll
            for (int k = 0; k < 4; k++) {
                int px  = wm + mt * 16 + (lane >> 2) + ((k & 2) ? 8 : 0);
                int ocl = wn + nt * 8 + (lane & 3) * 2 + (k & 1);
                so[ocl * 132 + px] = acc[mt][nt][k];
            }
    __syncthreads();

    const int ocl = tid >> 1, pxb = (tid & 1) * 64;
    const float bv = bias[oc0 + ocl];
    const float gsc = 1.41421356237309515f;
    float* dst = out + (((size_t)(b * COUT + oc0 + ocl) * 64) + hb + (tid & 1)) * 64;
#pragma unroll
    for (int j = 0; j < 64; j += 4) {
        float4 v = *(const float4*)(so + ocl * 132 + pxb + j);
        v.x = ((v.x + bv) > 0.f ? (v.x + bv) : 0.2f * (v.x + bv)) * gsc;
        v.y = ((v.y + bv) > 0.f ? (v.y + bv) : 0.2f * (v.y + bv)) * gsc;
        v.z = ((v.z + bv) > 0.f ? (v.z + bv) : 0.2f * (v.z + bv)) * gsc;
        v.w = ((v.w + bv) > 0.f ? (v.w + bv) : 0.2f * (v.w + bv)) * gsc;
        *(float4*)(dst + j) = v;
    }
}

// ---------------------------------------------------------------------------
extern "C" void kernel_launch(void* const* d_in, const int* in_sizes, int n_in,
                              void* d_out, int out_size) {
    const float* x    = (const float*)d_in[0];   // [16,256,128,128]
    const float* w    = (const float*)d_in[1];   // [3,3,256,512]
    const float* bias = (const float*)d_in[2];   // [512]
    float* out = (float*)d_out;                  // [16,512,64,64]

    cudaFuncSetAttribute(conv_mma_kernel,
                         cudaFuncAttributeMaxDynamicSharedMemorySize, SMEM_BYTES);

    blur_kernel<<<dim3(5, 17, B_ * 16), dim3(32, 8)>>>(x);
    wprep_kernel<<<dim3(16, 8, 9), dim3(32, 8)>>>(w);
    conv_mma_kernel<<<dim3(32, 4, B_), 256, SMEM_BYTES>>>(bias, out);
}

// round 6
// speedup vs baseline: 7.6111x; 1.5825x over previous
#include <cuda_runtime.h>
#include <cuda_fp16.h>
#include <cstdint>

#define B_    16
#define CIN   256
#define COUT  512
#define HB2   129   // blurred H/W

// Scratch: blurred intermediate NHWC fp16; weights [tap][oc][cin] fp16.
static __device__ __align__(128) __half g_x[(size_t)B_ * HB2 * HB2 * CIN];
static __device__ __align__(128) __half g_w[9 * COUT * CIN];

// ---------------------------------------------------------------------------
__device__ __forceinline__ uint32_t smem_u32(const void* p) {
    uint32_t a;
    asm("{ .reg .u64 t; cvta.to.shared.u64 t, %1; cvt.u32.u64 %0, t; }" : "=r"(a) : "l"(p));
    return a;
}
__device__ __forceinline__ void cp16(uint32_t d, const void* s) {
    asm volatile("cp.async.cg.shared.global [%0], [%1], 16;" :: "r"(d), "l"(s));
}
__device__ __forceinline__ void cp_commit() {
    asm volatile("cp.async.commit_group;" ::: "memory");
}
__device__ __forceinline__ void cp_wait2() {
    asm volatile("cp.async.wait_group 2;" ::: "memory");
}
__device__ __forceinline__ void ldsm4(uint32_t* r, uint32_t a) {
    asm volatile("ldmatrix.sync.aligned.m8n8.x4.shared.b16 {%0,%1,%2,%3}, [%4];"
                 : "=r"(r[0]), "=r"(r[1]), "=r"(r[2]), "=r"(r[3]) : "r"(a));
}
__device__ __forceinline__ void mma16816(float* c, const uint32_t* a, const uint32_t* b) {
    asm volatile(
        "mma.sync.aligned.m16n8k16.row.col.f32.f16.f16.f32 "
        "{%0,%1,%2,%3}, {%4,%5,%6,%7}, {%8,%9}, {%0,%1,%2,%3};"
        : "+f"(c[0]), "+f"(c[1]), "+f"(c[2]), "+f"(c[3])
        : "r"(a[0]), "r"(a[1]), "r"(a[2]), "r"(a[3]), "r"(b[0]), "r"(b[1]));
}

// ---------------------------------------------------------------------------
// Stage 1: separable 4x4 blur, NCHW fp32 -> NHWC fp16.
// Warp = one channel sweeping the full image top-to-bottom.
// Per input row: 1 LDG.128 (lane covers 4 cols) + 3 shuffles -> H-pass in
// registers; V-pass via 4-deep register ring. Outputs staged 8 rows at a
// time in smem [row][w][c] and flushed as 16B-coalesced NHWC stores.
// Block: 8 warps = 8 channels. Grid: 16 b x 32 channel-groups = 512.
// ---------------------------------------------------------------------------
__global__ void __launch_bounds__(256) blur_kernel(const float* __restrict__ x) {
    __shared__ __half stage[8][132][8];   // [oh&7][w][c]  (~16.9KB)
    const int b   = blockIdx.x >> 5;
    const int c0  = (blockIdx.x & 31) * 8;
    const int lane = threadIdx.x;         // 0..31 -> cols 4*lane..4*lane+3
    const int c    = threadIdx.y;         // 0..7  -> channel c0+c
    const float* xc = x + ((size_t)(b * CIN + c0 + c)) * (128 * 128);

    float ring[4][4];
    float ringE[4];
#pragma unroll
    for (int j = 0; j < 4; j++) {
        ringE[j] = 0.f;
#pragma unroll
        for (int k = 0; k < 4; k++) ring[j][k] = 0.f;
    }

    for (int r4 = 0; r4 < 132; r4 += 4) {
#pragma unroll
        for (int u = 0; u < 4; u++) {
            const int r = r4 + u;
            float4 q = make_float4(0.f, 0.f, 0.f, 0.f);
            if (r < 128) q = *(const float4*)(xc + r * 128 + lane * 4);
            float pz = __shfl_up_sync(0xffffffffu, q.z, 1);
            float pw = __shfl_up_sync(0xffffffffu, q.w, 1);
            float nx = __shfl_down_sync(0xffffffffu, q.x, 1);
            if (lane == 0)  { pz = 0.f; pw = 0.f; }
            if (lane == 31) { nx = 0.f; }
            // H-pass: hb[k] for w = 4*lane+k
            ring[u][0] = 0.125f * (pz + q.y)  + 0.375f * (pw + q.x);
            ring[u][1] = 0.125f * (pw + q.z)  + 0.375f * (q.x + q.y);
            ring[u][2] = 0.125f * (q.x + q.w) + 0.375f * (q.y + q.z);
            ring[u][3] = 0.125f * (q.y + nx)  + 0.375f * (q.z + q.w);
            ringE[u]   = 0.125f * q.z + 0.375f * q.w;   // w=128 (lane31 only used)

            if (r >= 1 && r <= 129) {
                // V-pass: oh = r-1 uses hb rows r-3..r = ring slots (u+1..u+3,u)&3
                const int s0 = (u + 1) & 3, s1 = (u + 2) & 3, s2 = (u + 3) & 3, s3 = u;
                const int ohm = (r - 1) & 7;
#pragma unroll
                for (int k = 0; k < 4; k++) {
                    float o = 0.125f * (ring[s0][k] + ring[s3][k])
                            + 0.375f * (ring[s1][k] + ring[s2][k]);
                    stage[ohm][4 * lane + k][c] = __float2half_rn(o);
                }
                if (lane == 31) {
                    float oE = 0.125f * (ringE[s0] + ringE[s3])
                             + 0.375f * (ringE[s1] + ringE[s2]);
                    stage[ohm][128][c] = __float2half_rn(oE);
                }
            }
            // Flush completed 8-row group (oh r-8..r-1) at r = 8,16,...,128
            if ((r & 7) == 0 && r >= 8 && r <= 128) {
                __syncthreads();
                const int row = (threadIdx.y * 32 + lane) >> 5;  // = c
                const int oh = (r - 8) + row;
                for (int w = lane; w < 129; w += 32) {
                    uint4 v = *(const uint4*)&stage[row][w][0];
                    *(uint4*)(g_x + ((size_t)(b * HB2 + oh) * HB2 + w) * CIN + c0) = v;
                }
                __syncthreads();
            }
        }
    }
    // Final flush: oh = 128 (stage row 0)
    __syncthreads();
    if (threadIdx.y == 0) {
        for (int w = lane; w < 129; w += 32) {
            uint4 v = *(const uint4*)&stage[0][w][0];
            *(uint4*)(g_x + ((size_t)(b * HB2 + 128) * HB2 + w) * CIN + c0) = v;
        }
    }
}

// ---------------------------------------------------------------------------
// Weight prep: w[3][3][CIN][COUT] fp32 -> g_w[tap][COUT][CIN] fp16, * 1/48.
// ---------------------------------------------------------------------------
__global__ void __launch_bounds__(256) wprep_kernel(const float* __restrict__ w) {
    __shared__ float t[32][33];
    const int tap = blockIdx.z, o0 = blockIdx.x * 32, cb0 = blockIdx.y * 32;
    const int tx = threadIdx.x, ty = threadIdx.y;
    const float sc = 1.0f / 48.0f;
    for (int r = ty; r < 32; r += 8)
        t[r][tx] = w[((size_t)tap * CIN + cb0 + r) * COUT + o0 + tx] * sc;
    __syncthreads();
    for (int r = ty; r < 32; r += 8)
        g_w[((size_t)tap * COUT + o0 + r) * CIN + cb0 + tx] = __float2half_rn(t[tx][r]);
}

// ---------------------------------------------------------------------------
// Stage 2: implicit GEMM via mma.sync (fp16 in, fp32 accum), single pass.
// CTA: 256 thr, tile M=128 px x N=128 oc. K=2304 in 72 chunks of 32.
// 4-stage cp.async ring, ONE __syncthreads per stage, wait_group 2.
// SMEM stride 40 fp16 (80B rows): conflict-free ldmatrix. 2 CTAs/SM.
// ---------------------------------------------------------------------------
#define TSTR  40                    // fp16 elements per smem row
#define STGB  20480                 // (128 A-rows + 128 B-rows) * 80B
#define SMEM_BYTES (4 * STGB)       // 81920

__global__ void __launch_bounds__(256, 2) conv_mma_kernel(
    const float* __restrict__ bias, float* __restrict__ out)
{
    extern __shared__ char smem[];
    const uint32_t sA = smem_u32(smem);
    const int tid = threadIdx.x, lane = tid & 31, wid = tid >> 5;
    const int hb  = blockIdx.x * 2;     // 2 output rows per CTA
    const int oc0 = blockIdx.y * 128;
    const int b   = blockIdx.z;
    const int wm  = (wid & 3) * 32;     // warp m offset
    const int wn  = (wid >> 2) * 64;    // warp n offset

    float acc[2][8][4];
#pragma unroll
    for (int i = 0; i < 2; i++)
#pragma unroll
        for (int j = 0; j < 8; j++)
#pragma unroll
            for (int k = 0; k < 4; k++) acc[i][j][k] = 0.f;

    // Load mapping: thread -> row r (0..127), k-half hk (16 fp16 = 32B).
    const int r  = tid >> 1;
    const int hk = tid & 1;
    const int oh = hb + (r >> 6), ow = r & 63;

#define ISSUE_LOADS(chunk, stg)                                                  \
    {                                                                            \
        const int tap = (chunk) >> 3, c0 = ((chunk) & 7) << 5;                   \
        const int kh = tap / 3, kw = tap - kh * 3;                               \
        const size_t ao = (((size_t)(b * HB2 + 2 * oh + kh)) * HB2               \
                           + (2 * ow + kw)) * CIN + c0 + hk * 16;                \
        const size_t bo = ((size_t)(tap * COUT + oc0 + r)) * CIN + c0 + hk * 16; \
        const uint32_t d = sA + (stg) * STGB + r * 80 + hk * 32;                 \
        cp16(d, g_x + ao);              cp16(d + 16, g_x + ao + 8);              \
        const uint32_t e = d + 10240;                                            \
        cp16(e, g_w + bo);              cp16(e + 16, g_w + bo + 8);              \
    }

    ISSUE_LOADS(0, 0); cp_commit();
    ISSUE_LOADS(1, 1); cp_commit();
    ISSUE_LOADS(2, 2); cp_commit();

    for (int i = 0; i < 72; i++) {
        cp_wait2();
        __syncthreads();
        const uint32_t base = sA + (i & 3) * STGB;

#pragma unroll
        for (int ks = 0; ks < 32; ks += 16) {
            uint32_t af[2][4], bf[4][4];
#pragma unroll
            for (int mt = 0; mt < 2; mt++) {
                uint32_t a = base + ((wm + mt * 16 + (lane & 15)) * TSTR
                                     + ks + ((lane & 16) >> 1)) * 2;
                ldsm4(af[mt], a);
            }
#pragma unroll
            for (int bt = 0; bt < 4; bt++) {
                uint32_t a = base + 10240
                           + ((wn + bt * 16 + (lane & 7) + ((lane & 16) >> 1)) * TSTR
                              + ks + (lane & 8)) * 2;
                ldsm4(bf[bt], a);
            }
#pragma unroll
            for (int mt = 0; mt < 2; mt++)
#pragma unroll
                for (int bt = 0; bt < 4; bt++)
#pragma unroll
                    for (int h = 0; h < 2; h++)
                        mma16816(acc[mt][bt * 2 + h], af[mt], &bf[bt][2 * h]);
        }
        if (i + 3 < 72) ISSUE_LOADS(i + 3, (i + 3) & 3);
        cp_commit();
    }
    __syncthreads();   // all warps done reading stages before smem reuse

    // Epilogue: stage [oc_local][px] fp32 in smem, then coalesced writes.
    float* so = (float*)smem;           // 128 x 132 floats = 67.6KB <= 80KB
#pragma unroll
    for (int mt = 0; mt < 2; mt++)
#pragma unroll
        for (int nt = 0; nt < 8; nt++)
#pragma unroll
            for (int k = 0; k < 4; k++) {
                int px  = wm + mt * 16 + (lane >> 2) + ((k & 2) ? 8 : 0);
                int ocl = wn + nt * 8 + (lane & 3) * 2 + (k & 1);
                so[ocl * 132 + px] = acc[mt][nt][k];
            }
    __syncthreads();

    const int ocl = tid >> 1, pxb = (tid & 1) * 64;
    const float bv = bias[oc0 + ocl];
    const float gsc = 1.41421356237309515f;
    float* dst = out + (((size_t)(b * COUT + oc0 + ocl) * 64) + hb + (tid & 1)) * 64;
#pragma unroll
    for (int j = 0; j < 64; j += 4) {
        float4 v = *(const float4*)(so + ocl * 132 + pxb + j);
        v.x = ((v.x + bv) > 0.f ? (v.x + bv) : 0.2f * (v.x + bv)) * gsc;
        v.y = ((v.y + bv) > 0.f ? (v.y + bv) : 0.2f * (v.y + bv)) * gsc;
        v.z = ((v.z + bv) > 0.f ? (v.z + bv) : 0.2f * (v.z + bv)) * gsc;
        v.w = ((v.w + bv) > 0.f ? (v.w + bv) : 0.2f * (v.w + bv)) * gsc;
        *(float4*)(dst + j) = v;
    }
}

// ---------------------------------------------------------------------------
extern "C" void kernel_launch(void* const* d_in, const int* in_sizes, int n_in,
                              void* d_out, int out_size) {
    const float* x    = (const float*)d_in[0];   // [16,256,128,128]
    const float* w    = (const float*)d_in[1];   // [3,3,256,512]
    const float* bias = (const float*)d_in[2];   // [512]
    float* out = (float*)d_out;                  // [16,512,64,64]

    cudaFuncSetAttribute(conv_mma_kernel,
                         cudaFuncAttributeMaxDynamicSharedMemorySize, SMEM_BYTES);

    blur_kernel<<<512, dim3(32, 8)>>>(x);
    wprep_kernel<<<dim3(16, 8, 9), dim3(32, 8)>>>(w);
    conv_mma_kernel<<<dim3(32, 4, B_), 256, SMEM_BYTES>>>(bias, out);
}